// round 4
// baseline (speedup 1.0000x reference)
#include <cuda_runtime.h>
#include <math.h>
#include <stdint.h>

typedef unsigned long long ull;

// Problem constants
#define BQ    512
#define EDIM  512
#define CDIM  70722
#define TWC   (2*CDIM)
#define EPSF  0.001f
#define HF    0.333f
#define SF    64.0f
#define MMARG 0.4f
#define TALPHA 1.0f

// Scratch
__device__ float d_cos2t[BQ];
__device__ float d_gang[BQ];
__device__ float d_gadd[BQ];

// ---------------------------------------------------------------------------
// K2: cos2_tgt[b] = clip( <emb[b,:], k1[:,label[b]]> / ||k1[:,label[b]]|| )
// ---------------------------------------------------------------------------
__global__ void cos2_kernel(const float* __restrict__ kern,
                            const float* __restrict__ emb,
                            const int*   __restrict__ label) {
    int b = blockIdx.x, t = threadIdx.x;
    int lab = label[b];
    const float* col = kern + (size_t)CDIM + lab;  // t=1 plane
    float ss = 0.f, dt = 0.f;
    for (int e = t; e < EDIM; e += 128) {
        float v = col[(size_t)e * TWC];
        ss += v * v;
        dt += emb[b * EDIM + e] * v;
    }
    __shared__ float sss[128], sdt[128];
    sss[t] = ss; sdt[t] = dt;
    __syncthreads();
    for (int o = 64; o > 0; o >>= 1) {
        if (t < o) { sss[t] += sss[t+o]; sdt[t] += sdt[t+o]; }
        __syncthreads();
    }
    if (t == 0) {
        float cz = sdt[0] * rsqrtf(sss[0]);
        d_cos2t[b] = fminf(fmaxf(cz, -1.0f + EPSF), 1.0f - EPSF);
    }
}

// ---------------------------------------------------------------------------
// K3: batch statistics + cw_margin output
// ---------------------------------------------------------------------------
__global__ void stats_kernel(const float* __restrict__ norms,
                             const int*   __restrict__ label,
                             float* __restrict__ out) {
    __shared__ float sn[BQ];
    __shared__ int   lab[BQ];
    __shared__ float red[BQ];
    int t = threadIdx.x;
    float x = fminf(fmaxf(norms[t], 0.001f), 100.0f);
    sn[t] = x; lab[t] = label[t]; red[t] = x;
    __syncthreads();
    for (int o = 256; o > 0; o >>= 1) { if (t < o) red[t] += red[t+o]; __syncthreads(); }
    float mean = red[0] * (1.0f / BQ);
    __syncthreads();
    float d = x - mean;
    red[t] = d * d;
    __syncthreads();
    for (int o = 256; o > 0; o >>= 1) { if (t < o) red[t] += red[t+o]; __syncthreads(); }
    float stdv = sqrtf(red[0] / (float)(BQ - 1));
    float batch_mean = mean * TALPHA + (1.0f - TALPHA) * 20.0f;
    float batch_std  = stdv * TALPHA + (1.0f - TALPHA) * 10.0f;
    int ml = lab[t];
    float s = 0.f; int cnt = 0;
    for (int j = 0; j < BQ; ++j) if (lab[j] == ml) { s += sn[j]; cnt++; }
    float cwm = (s / (float)cnt) * TALPHA + (1.0f - TALPHA) * 20.0f;
    float inv = 1.0f / (batch_std + EPSF);
    float ms = fminf(fmaxf((x - batch_mean) * inv * HF, -1.0f), 1.0f);
    d_gang[t] = -MMARG * ms;
    d_gadd[t] =  MMARG + MMARG * ms;
    out[(size_t)2 * BQ * CDIM + t] = fminf(fmaxf((x - cwm) * inv, -1.0f), 1.0f) * HF;
}

// ---------------------------------------------------------------------------
// K4: packed-f32x2 GEMM + fused column norms + epilogue.
// BM=128, BN=128, BK=16, 256 threads, 8x8 per-thread tile (as 8x4 f32x2).
// ---------------------------------------------------------------------------
__global__ __launch_bounds__(256, 2)
void gemm_kernel(const float* __restrict__ A,       // emb [512,512]
                 const float* __restrict__ Kn,      // kernel t=0 plane (stride TWC)
                 float* __restrict__ out) {
    __shared__ ull   As2[16][128];   // duplicated {a,a} pairs, 16KB
    __shared__ float Bs[16][128];    // 8KB
    __shared__ float sinv[128];
    const int t = threadIdx.x;
    const int mbase = blockIdx.x * 128;
    const int cbase = blockIdx.y * 128;
    const int tm = (t >> 4) * 8;
    const int tn = (t & 15) * 8;

    ull acc2[8][4];
    #pragma unroll
    for (int i = 0; i < 8; ++i)
        #pragma unroll
        for (int j = 0; j < 4; ++j) acc2[i][j] = 0ULL;

    float ssq = 0.0f;   // column sum-of-squares (valid in threads t<128)

    for (int kb = 0; kb < EDIM; kb += 16) {
        // ---- A tile: 128x16, duplicated into As2[k][m] = {a,a} ----
        #pragma unroll
        for (int i = 0; i < 2; ++i) {
            int u  = t + i * 256;          // 0..511
            int m  = u >> 2;               // 0..127
            int kq = (u & 3) << 2;         // 0,4,8,12
            const float4 v = *(const float4*)&A[(size_t)(mbase + m) * EDIM + kb + kq];
            *(float2*)&As2[kq+0][m] = make_float2(v.x, v.x);
            *(float2*)&As2[kq+1][m] = make_float2(v.y, v.y);
            *(float2*)&As2[kq+2][m] = make_float2(v.z, v.z);
            *(float2*)&As2[kq+3][m] = make_float2(v.w, v.w);
        }
        // ---- B tile: 16x128, coalesced over c ----
        #pragma unroll
        for (int i = 0; i < 8; ++i) {
            int u = t + i * 256;           // 0..2047
            int e = u >> 7;                // 0..15
            int n = u & 127;
            int c = cbase + n;
            Bs[e][n] = (c < CDIM) ? Kn[(size_t)(kb + e) * TWC + c] : 0.0f;
        }
        __syncthreads();

        // ---- fused column-norm partial: thread t<128 owns column n=t ----
        if (t < 128) {
            #pragma unroll
            for (int k = 0; k < 16; ++k) {
                float v = Bs[k][t];
                ssq += v * v;
            }
        }

        // ---- math: 32 fma.f32x2 per k-step ----
        #pragma unroll
        for (int k = 0; k < 16; ++k) {
            ull a2[8], b2[8];
            {
                ulonglong2 p0 = *(const ulonglong2*)&As2[k][tm + 0];
                ulonglong2 p1 = *(const ulonglong2*)&As2[k][tm + 2];
                ulonglong2 p2 = *(const ulonglong2*)&As2[k][tm + 4];
                ulonglong2 p3 = *(const ulonglong2*)&As2[k][tm + 6];
                a2[0]=p0.x; a2[1]=p0.y; a2[2]=p1.x; a2[3]=p1.y;
                a2[4]=p2.x; a2[5]=p2.y; a2[6]=p3.x; a2[7]=p3.y;
                ulonglong2 q0 = *(const ulonglong2*)&Bs[k][tn + 0];
                ulonglong2 q1 = *(const ulonglong2*)&Bs[k][tn + 4];
                b2[0]=q0.x; b2[1]=q0.y; b2[2]=q1.x; b2[3]=q1.y;
            }
            #pragma unroll
            for (int i = 0; i < 8; ++i)
                #pragma unroll
                for (int j = 0; j < 4; ++j)
                    asm("fma.rn.f32x2 %0, %1, %2, %0;"
                        : "+l"(acc2[i][j]) : "l"(a2[i]), "l"(b2[j]));
        }
        __syncthreads();
    }

    // ---- column inverse norms -> smem ----
    if (t < 128) sinv[t] = rsqrtf(ssq);
    __syncthreads();

    // ---- epilogue ----
    float inv[8];
    #pragma unroll
    for (int j = 0; j < 8; ++j) inv[j] = sinv[tn + j];
    const float lo = -1.0f + EPSF, hi = 1.0f - EPSF;
    const bool full = (cbase + 128 <= CDIM);
    #pragma unroll
    for (int i = 0; i < 8; ++i) {
        int r = mbase + tm + i;
        float v[8];
        #pragma unroll
        for (int j = 0; j < 4; ++j) {
            float x0 = __uint_as_float((unsigned)(acc2[i][j] & 0xffffffffULL));
            float x1 = __uint_as_float((unsigned)(acc2[i][j] >> 32));
            x0 = fminf(fmaxf(x0 * inv[2*j+0], lo), hi) * SF;
            x1 = fminf(fmaxf(x1 * inv[2*j+1], lo), hi) * SF;
            v[2*j+0] = x0; v[2*j+1] = x1;
        }
        size_t base = (size_t)r * CDIM + cbase + tn;
        float* o1 = out + base;
        float* o2 = out + (size_t)BQ * CDIM + base;
        if (full) {
            #pragma unroll
            for (int j = 0; j < 8; j += 2) {
                float2 p = make_float2(v[j], v[j+1]);
                *(float2*)(o1 + j) = p;
                *(float2*)(o2 + j) = p;
            }
        } else {
            #pragma unroll
            for (int j = 0; j < 8; ++j) {
                if (cbase + tn + j < CDIM) { o1[j] = v[j]; o2[j] = v[j]; }
            }
        }
    }
}

// ---------------------------------------------------------------------------
// K5: label-column fixup (computes its own column norm now)
// ---------------------------------------------------------------------------
__global__ void fixup_kernel(const float* __restrict__ kern,
                             const float* __restrict__ emb,
                             const int*   __restrict__ label,
                             float* __restrict__ out) {
    int b = blockIdx.x, t = threadIdx.x;
    int lab = label[b];
    const float* col = kern + lab;  // t=0 plane
    float dt = 0.f, ss = 0.f;
    for (int e = t; e < EDIM; e += 128) {
        float v = col[(size_t)e * TWC];
        dt += emb[b * EDIM + e] * v;
        ss += v * v;
    }
    __shared__ float sdt[128], sss[128];
    sdt[t] = dt; sss[t] = ss;
    __syncthreads();
    for (int o = 64; o > 0; o >>= 1) {
        if (t < o) { sdt[t] += sdt[t+o]; sss[t] += sss[t+o]; }
        __syncthreads();
    }
    if (t == 0) {
        const float lo = -1.0f + EPSF, hi = 1.0f - EPSF;
        const float thlo = EPSF, thhi = (float)M_PI - EPSF;
        float gang = d_gang[b], gadd = d_gadd[b];
        float w1 = sdt[0] * rsqrtf(sss[0]);
        w1 = fminf(fmaxf(w1, lo), hi);
        float th1 = fminf(fmaxf(acosf(w1) + gang, thlo), thhi);
        out[(size_t)b * CDIM + lab] = (cosf(th1) - gadd) * SF;
        float w2 = d_cos2t[b];
        float th2 = fminf(fmaxf(acosf(w2) + gang, thlo), thhi);
        out[(size_t)BQ * CDIM + (size_t)b * CDIM + lab] = (cosf(th2) - gadd) * SF;
    }
}

// ---------------------------------------------------------------------------
extern "C" void kernel_launch(void* const* d_in, const int* in_sizes, int n_in,
                              void* d_out, int out_size) {
    const float* emb   = (const float*)d_in[0];  // [512, 512]
    const float* norms = (const float*)d_in[1];  // [512, 1]
    const int*   label = (const int*)  d_in[2];  // [512]
    const float* kern  = (const float*)d_in[3];  // [512, 2, 70722]
    float* out = (float*)d_out;

    cos2_kernel<<<BQ, 128>>>(kern, emb, label);
    stats_kernel<<<1, BQ>>>(norms, label, out);
    gemm_kernel<<<dim3(4, (CDIM + 127) / 128), 256>>>(emb, kern, out);
    fixup_kernel<<<BQ, 128>>>(kern, emb, label, out);
}

// round 5
// speedup vs baseline: 1.9587x; 1.9587x over previous
#include <cuda_runtime.h>
#include <math.h>
#include <stdint.h>

// Problem constants
#define BQ    512
#define EDIM  512
#define CDIM  70722
#define TWC   (2*CDIM)
#define EPSF  0.001f
#define HF    0.333f
#define SF    64.0f
#define MMARG 0.4f
#define TALPHA 1.0f

// GEMM tile config
#define BM 128
#define BN 128
#define BK 32
#define RS 40           // smem row stride in bf16 halves (80B, 16B-multiple)

// Scratch
__device__ float d_cos2t[BQ];
__device__ float d_gang[BQ];
__device__ float d_gadd[BQ];

// ============================ helpers ======================================
__device__ __forceinline__ uint32_t smem_u32(const void* p) {
    uint32_t a;
    asm("{ .reg .u64 t; cvta.to.shared.u64 t, %1; cvt.u32.u64 %0, t; }" : "=r"(a) : "l"(p));
    return a;
}
__device__ __forceinline__ void ldsm4(uint32_t* r, uint32_t addr) {
    asm volatile("ldmatrix.sync.aligned.m8n8.x4.shared.b16 {%0,%1,%2,%3}, [%4];"
        : "=r"(r[0]), "=r"(r[1]), "=r"(r[2]), "=r"(r[3]) : "r"(addr));
}
__device__ __forceinline__ void mma_bf16(float* c, const uint32_t* a, const uint32_t* b) {
    asm volatile(
        "mma.sync.aligned.m16n8k16.row.col.f32.bf16.bf16.f32 "
        "{%0,%1,%2,%3}, {%4,%5,%6,%7}, {%8,%9}, {%0,%1,%2,%3};"
        : "+f"(c[0]), "+f"(c[1]), "+f"(c[2]), "+f"(c[3])
        : "r"(a[0]), "r"(a[1]), "r"(a[2]), "r"(a[3]), "r"(b[0]), "r"(b[1]));
}
// split pair (x0,x1) into packed bf16 hi-parts and bf16 residuals (lo at low half)
__device__ __forceinline__ void split2(float x0, float x1, uint32_t& hp, uint32_t& lp) {
    asm("cvt.rn.bf16x2.f32 %0, %1, %2;" : "=r"(hp) : "f"(x1), "f"(x0));
    float h0 = __uint_as_float(hp << 16);
    float h1 = __uint_as_float(hp & 0xffff0000u);
    float r0 = x0 - h0, r1 = x1 - h1;
    asm("cvt.rn.bf16x2.f32 %0, %1, %2;" : "=r"(lp) : "f"(r1), "f"(r0));
}

// ---------------------------------------------------------------------------
// K2: cos2_tgt[b]
// ---------------------------------------------------------------------------
__global__ void cos2_kernel(const float* __restrict__ kern,
                            const float* __restrict__ emb,
                            const int*   __restrict__ label) {
    int b = blockIdx.x, t = threadIdx.x;
    int lab = label[b];
    const float* col = kern + (size_t)CDIM + lab;  // t=1 plane
    float ss = 0.f, dt = 0.f;
    for (int e = t; e < EDIM; e += 128) {
        float v = col[(size_t)e * TWC];
        ss += v * v;
        dt += emb[b * EDIM + e] * v;
    }
    __shared__ float sss[128], sdt[128];
    sss[t] = ss; sdt[t] = dt;
    __syncthreads();
    for (int o = 64; o > 0; o >>= 1) {
        if (t < o) { sss[t] += sss[t+o]; sdt[t] += sdt[t+o]; }
        __syncthreads();
    }
    if (t == 0) {
        float cz = sdt[0] * rsqrtf(sss[0]);
        d_cos2t[b] = fminf(fmaxf(cz, -1.0f + EPSF), 1.0f - EPSF);
    }
}

// ---------------------------------------------------------------------------
// K3: batch statistics + cw_margin output
// ---------------------------------------------------------------------------
__global__ void stats_kernel(const float* __restrict__ norms,
                             const int*   __restrict__ label,
                             float* __restrict__ out) {
    __shared__ float sn[BQ];
    __shared__ int   lab[BQ];
    __shared__ float red[BQ];
    int t = threadIdx.x;
    float x = fminf(fmaxf(norms[t], 0.001f), 100.0f);
    sn[t] = x; lab[t] = label[t]; red[t] = x;
    __syncthreads();
    for (int o = 256; o > 0; o >>= 1) { if (t < o) red[t] += red[t+o]; __syncthreads(); }
    float mean = red[0] * (1.0f / BQ);
    __syncthreads();
    float d = x - mean;
    red[t] = d * d;
    __syncthreads();
    for (int o = 256; o > 0; o >>= 1) { if (t < o) red[t] += red[t+o]; __syncthreads(); }
    float stdv = sqrtf(red[0] / (float)(BQ - 1));
    float batch_mean = mean * TALPHA + (1.0f - TALPHA) * 20.0f;
    float batch_std  = stdv * TALPHA + (1.0f - TALPHA) * 10.0f;
    int ml = lab[t];
    float s = 0.f; int cnt = 0;
    for (int j = 0; j < BQ; ++j) if (lab[j] == ml) { s += sn[j]; cnt++; }
    float cwm = (s / (float)cnt) * TALPHA + (1.0f - TALPHA) * 20.0f;
    float inv = 1.0f / (batch_std + EPSF);
    float ms = fminf(fmaxf((x - batch_mean) * inv * HF, -1.0f), 1.0f);
    d_gang[t] = -MMARG * ms;
    d_gadd[t] =  MMARG + MMARG * ms;
    out[(size_t)2 * BQ * CDIM + t] = fminf(fmaxf((x - cwm) * inv, -1.0f), 1.0f) * HF;
}

// ---------------------------------------------------------------------------
// K4: mma.sync bf16-split GEMM + fused column norms + epilogue.
// 256 threads = 8 warps (2m x 4n). Warp tile 64x32. Chunks of K=32.
// ---------------------------------------------------------------------------
__global__ __launch_bounds__(256, 1)
void gemm_kernel(const float* __restrict__ A,       // emb [512,512]
                 const float* __restrict__ Kn,      // kernel t=0 plane (stride TWC)
                 float* __restrict__ out) {
    __shared__ __align__(16) uint16_t Ah[BM*RS], Al[BM*RS];
    __shared__ __align__(16) uint16_t Bh[BN*RS], Bl[BN*RS];
    __shared__ float ssqp[256];
    __shared__ float sinv[BN];

    const int t = threadIdx.x;
    const int lane = t & 31;
    const int wid = t >> 5;
    const int mbase = blockIdx.x * BM;
    const int cbase = blockIdx.y * BN;
    const int wm = (wid >> 2) * 64;
    const int wn = (wid & 3) * 32;

    float acc[4][4][4];
    #pragma unroll
    for (int i = 0; i < 4; ++i)
        #pragma unroll
        for (int j = 0; j < 4; ++j)
            #pragma unroll
            for (int r = 0; r < 4; ++r) acc[i][j][r] = 0.f;

    float ssq = 0.f;
    const int bn  = t & 127;
    const int bkh = (t >> 7) * 16;
    const int bc  = cbase + bn;
    const bool bvalid = bc < CDIM;

    const uint32_t aH = smem_u32(Ah), aL = smem_u32(Al);
    const uint32_t bH = smem_u32(Bh), bL = smem_u32(Bl);

    // ldmatrix lane addressing (constant per thread)
    const int a_row  = wm + (lane & 15);
    const int a_coff = (lane >> 4) * 8;
    const int b_n    = wn + ((lane >> 4) << 3) + (lane & 7);
    const int b_koff = ((lane >> 3) & 1) * 8;

    for (int kb = 0; kb < EDIM; kb += BK) {
        // ---- A tile: 128x32 fp32 -> bf16 hi/lo, coalesced float4 loads ----
        #pragma unroll
        for (int i = 0; i < 4; ++i) {
            int u = t + i * 256;           // 0..1023
            int m = u >> 3, q = u & 7;     // q = float4 index
            float4 v = *(const float4*)&A[(size_t)(mbase + m) * EDIM + kb + q * 4];
            uint32_t h01, l01, h23, l23;
            split2(v.x, v.y, h01, l01);
            split2(v.z, v.w, h23, l23);
            uint2 hp = make_uint2(h01, h23), lp = make_uint2(l01, l23);
            *(uint2*)&Ah[m * RS + q * 4] = hp;
            *(uint2*)&Al[m * RS + q * 4] = lp;
        }
        // ---- B tile: 32k x 128n -> smem [n][k] bf16 hi/lo + ssq ----
        #pragma unroll
        for (int j = 0; j < 16; j += 2) {
            float v0 = 0.f, v1 = 0.f;
            if (bvalid) {
                const float* p = Kn + (size_t)(kb + bkh + j) * TWC + bc;
                v0 = p[0];
                v1 = p[TWC];
            }
            ssq += v0 * v0 + v1 * v1;
            uint32_t hp, lp;
            split2(v0, v1, hp, lp);
            *(uint32_t*)&Bh[bn * RS + bkh + j] = hp;
            *(uint32_t*)&Bl[bn * RS + bkh + j] = lp;
        }
        __syncthreads();

        // ---- math: 2 k-frags x (16 hh + 16 hl + 16 lh) mma ----
        #pragma unroll
        for (int kf = 0; kf < 2; ++kf) {
            const int kc = kf * 16;
            uint32_t ah[4][4], al[4][4], bhf[4][2], blf[4][2];
            #pragma unroll
            for (int mf = 0; mf < 4; ++mf) {
                uint32_t ad = ((uint32_t)((a_row + mf * 16) * RS + kc + a_coff)) * 2;
                ldsm4(ah[mf], aH + ad);
                ldsm4(al[mf], aL + ad);
            }
            {
                uint32_t bd0 = ((uint32_t)(b_n * RS + kc + b_koff)) * 2;
                uint32_t bd1 = ((uint32_t)((b_n + 16) * RS + kc + b_koff)) * 2;
                uint32_t r[4];
                ldsm4(r, bH + bd0);
                bhf[0][0]=r[0]; bhf[0][1]=r[1]; bhf[1][0]=r[2]; bhf[1][1]=r[3];
                ldsm4(r, bH + bd1);
                bhf[2][0]=r[0]; bhf[2][1]=r[1]; bhf[3][0]=r[2]; bhf[3][1]=r[3];
                ldsm4(r, bL + bd0);
                blf[0][0]=r[0]; blf[0][1]=r[1]; blf[1][0]=r[2]; blf[1][1]=r[3];
                ldsm4(r, bL + bd1);
                blf[2][0]=r[0]; blf[2][1]=r[1]; blf[3][0]=r[2]; blf[3][1]=r[3];
            }
            #pragma unroll
            for (int mf = 0; mf < 4; ++mf)
                #pragma unroll
                for (int nf = 0; nf < 4; ++nf)
                    mma_bf16(acc[mf][nf], ah[mf], bhf[nf]);
            #pragma unroll
            for (int mf = 0; mf < 4; ++mf)
                #pragma unroll
                for (int nf = 0; nf < 4; ++nf)
                    mma_bf16(acc[mf][nf], ah[mf], blf[nf]);
            #pragma unroll
            for (int mf = 0; mf < 4; ++mf)
                #pragma unroll
                for (int nf = 0; nf < 4; ++nf)
                    mma_bf16(acc[mf][nf], al[mf], bhf[nf]);
        }
        __syncthreads();
    }

    // ---- column inverse norms ----
    ssqp[t] = ssq;
    __syncthreads();
    if (t < 128) sinv[t] = rsqrtf(ssqp[t] + ssqp[t + 128]);
    __syncthreads();

    // ---- epilogue: clip*scale, dual-plane float2 stores ----
    const float lo = -1.0f + EPSF, hi = 1.0f - EPSF;
    float inv[4][2];
    #pragma unroll
    for (int nf = 0; nf < 4; ++nf) {
        int c0 = wn + nf * 8 + (lane & 3) * 2;
        inv[nf][0] = sinv[c0];
        inv[nf][1] = sinv[c0 + 1];
    }
    #pragma unroll
    for (int mf = 0; mf < 4; ++mf) {
        int row0 = mbase + wm + mf * 16 + (lane >> 2);
        #pragma unroll
        for (int nf = 0; nf < 4; ++nf) {
            int col = cbase + wn + nf * 8 + (lane & 3) * 2;
            if (col < CDIM) {
                float v0 = fminf(fmaxf(acc[mf][nf][0] * inv[nf][0], lo), hi) * SF;
                float v1 = fminf(fmaxf(acc[mf][nf][1] * inv[nf][1], lo), hi) * SF;
                float v2 = fminf(fmaxf(acc[mf][nf][2] * inv[nf][0], lo), hi) * SF;
                float v3 = fminf(fmaxf(acc[mf][nf][3] * inv[nf][1], lo), hi) * SF;
                size_t o0 = (size_t)row0 * CDIM + col;
                size_t o1 = (size_t)(row0 + 8) * CDIM + col;
                *(float2*)(out + o0) = make_float2(v0, v1);
                *(float2*)(out + o1) = make_float2(v2, v3);
                *(float2*)(out + (size_t)BQ * CDIM + o0) = make_float2(v0, v1);
                *(float2*)(out + (size_t)BQ * CDIM + o1) = make_float2(v2, v3);
            }
        }
    }
}

// ---------------------------------------------------------------------------
// K5: label-column fixup (fp32-exact; overwrites GEMM values at labels)
// ---------------------------------------------------------------------------
__global__ void fixup_kernel(const float* __restrict__ kern,
                             const float* __restrict__ emb,
                             const int*   __restrict__ label,
                             float* __restrict__ out) {
    int b = blockIdx.x, t = threadIdx.x;
    int lab = label[b];
    const float* col = kern + lab;  // t=0 plane
    float dt = 0.f, ss = 0.f;
    for (int e = t; e < EDIM; e += 128) {
        float v = col[(size_t)e * TWC];
        dt += emb[b * EDIM + e] * v;
        ss += v * v;
    }
    __shared__ float sdt[128], sss[128];
    sdt[t] = dt; sss[t] = ss;
    __syncthreads();
    for (int o = 64; o > 0; o >>= 1) {
        if (t < o) { sdt[t] += sdt[t+o]; sss[t] += sss[t+o]; }
        __syncthreads();
    }
    if (t == 0) {
        const float lo = -1.0f + EPSF, hi = 1.0f - EPSF;
        const float thlo = EPSF, thhi = (float)M_PI - EPSF;
        float gang = d_gang[b], gadd = d_gadd[b];
        float w1 = sdt[0] * rsqrtf(sss[0]);
        w1 = fminf(fmaxf(w1, lo), hi);
        float th1 = fminf(fmaxf(acosf(w1) + gang, thlo), thhi);
        out[(size_t)b * CDIM + lab] = (cosf(th1) - gadd) * SF;
        float w2 = d_cos2t[b];
        float th2 = fminf(fmaxf(acosf(w2) + gang, thlo), thhi);
        out[(size_t)BQ * CDIM + (size_t)b * CDIM + lab] = (cosf(th2) - gadd) * SF;
    }
}

// ---------------------------------------------------------------------------
extern "C" void kernel_launch(void* const* d_in, const int* in_sizes, int n_in,
                              void* d_out, int out_size) {
    const float* emb   = (const float*)d_in[0];  // [512, 512]
    const float* norms = (const float*)d_in[1];  // [512, 1]
    const int*   label = (const int*)  d_in[2];  // [512]
    const float* kern  = (const float*)d_in[3];  // [512, 2, 70722]
    float* out = (float*)d_out;

    cos2_kernel<<<BQ, 128>>>(kern, emb, label);
    stats_kernel<<<1, BQ>>>(norms, label, out);
    gemm_kernel<<<dim3(4, (CDIM + BN - 1) / BN), 256>>>(emb, kern, out);
    fixup_kernel<<<BQ, 128>>>(kern, emb, label, out);
}

// round 6
// speedup vs baseline: 2.3827x; 1.2164x over previous
#include <cuda_runtime.h>
#include <math.h>
#include <stdint.h>

// Problem constants
#define BQ    512
#define EDIM  512
#define CDIM  70722
#define TWC   (2*CDIM)
#define EPSF  0.001f
#define HF    0.333f
#define SF    64.0f
#define MMARG 0.4f
#define TALPHA 1.0f

// GEMM tile config
#define BM 128
#define BN 128
#define BK 32
#define RS 40                       // smem row stride in halves (80B)
#define TILE_H   (BM*RS)            // halves per tile array
#define TILE_B   (TILE_H*2)         // 10240 bytes
#define BUF_B    (4*TILE_B)         // Ah,Al,Bh,Bl = 40960 bytes
#define SSQP_OFF (2*BUF_B)          // 81920
#define SINV_OFF (SSQP_OFF + 512*4) // 83968
#define SMEM_SZ  (SINV_OFF + BN*4)  // 84480

// Scratch
__device__ float d_cos2t[BQ];
__device__ float d_gang[BQ];
__device__ float d_gadd[BQ];

// ============================ helpers ======================================
__device__ __forceinline__ uint32_t smem_u32(const void* p) {
    uint32_t a;
    asm("{ .reg .u64 t; cvta.to.shared.u64 t, %1; cvt.u32.u64 %0, t; }" : "=r"(a) : "l"(p));
    return a;
}
__device__ __forceinline__ void ldsm4(uint32_t* r, uint32_t addr) {
    asm volatile("ldmatrix.sync.aligned.m8n8.x4.shared.b16 {%0,%1,%2,%3}, [%4];"
        : "=r"(r[0]), "=r"(r[1]), "=r"(r[2]), "=r"(r[3]) : "r"(addr));
}
__device__ __forceinline__ void mma_bf16(float* c, const uint32_t* a, const uint32_t* b) {
    asm volatile(
        "mma.sync.aligned.m16n8k16.row.col.f32.bf16.bf16.f32 "
        "{%0,%1,%2,%3}, {%4,%5,%6,%7}, {%8,%9}, {%0,%1,%2,%3};"
        : "+f"(c[0]), "+f"(c[1]), "+f"(c[2]), "+f"(c[3])
        : "r"(a[0]), "r"(a[1]), "r"(a[2]), "r"(a[3]), "r"(b[0]), "r"(b[1]));
}
__device__ __forceinline__ void split2(float x0, float x1, uint32_t& hp, uint32_t& lp) {
    asm("cvt.rn.bf16x2.f32 %0, %1, %2;" : "=r"(hp) : "f"(x1), "f"(x0));
    float h0 = __uint_as_float(hp << 16);
    float h1 = __uint_as_float(hp & 0xffff0000u);
    float r0 = x0 - h0, r1 = x1 - h1;
    asm("cvt.rn.bf16x2.f32 %0, %1, %2;" : "=r"(lp) : "f"(r1), "f"(r0));
}

// ---------------------------------------------------------------------------
// K2: cos2_tgt[b]
// ---------------------------------------------------------------------------
__global__ void cos2_kernel(const float* __restrict__ kern,
                            const float* __restrict__ emb,
                            const int*   __restrict__ label) {
    int b = blockIdx.x, t = threadIdx.x;
    int lab = label[b];
    const float* col = kern + (size_t)CDIM + lab;
    float ss = 0.f, dt = 0.f;
    for (int e = t; e < EDIM; e += 128) {
        float v = col[(size_t)e * TWC];
        ss += v * v;
        dt += emb[b * EDIM + e] * v;
    }
    __shared__ float sss[128], sdt[128];
    sss[t] = ss; sdt[t] = dt;
    __syncthreads();
    for (int o = 64; o > 0; o >>= 1) {
        if (t < o) { sss[t] += sss[t+o]; sdt[t] += sdt[t+o]; }
        __syncthreads();
    }
    if (t == 0) {
        float cz = sdt[0] * rsqrtf(sss[0]);
        d_cos2t[b] = fminf(fmaxf(cz, -1.0f + EPSF), 1.0f - EPSF);
    }
}

// ---------------------------------------------------------------------------
// K3: batch statistics + cw_margin output
// ---------------------------------------------------------------------------
__global__ void stats_kernel(const float* __restrict__ norms,
                             const int*   __restrict__ label,
                             float* __restrict__ out) {
    __shared__ float sn[BQ];
    __shared__ int   lab[BQ];
    __shared__ float red[BQ];
    int t = threadIdx.x;
    float x = fminf(fmaxf(norms[t], 0.001f), 100.0f);
    sn[t] = x; lab[t] = label[t]; red[t] = x;
    __syncthreads();
    for (int o = 256; o > 0; o >>= 1) { if (t < o) red[t] += red[t+o]; __syncthreads(); }
    float mean = red[0] * (1.0f / BQ);
    __syncthreads();
    float d = x - mean;
    red[t] = d * d;
    __syncthreads();
    for (int o = 256; o > 0; o >>= 1) { if (t < o) red[t] += red[t+o]; __syncthreads(); }
    float stdv = sqrtf(red[0] / (float)(BQ - 1));
    float batch_mean = mean * TALPHA + (1.0f - TALPHA) * 20.0f;
    float batch_std  = stdv * TALPHA + (1.0f - TALPHA) * 10.0f;
    int ml = lab[t];
    float s = 0.f; int cnt = 0;
    for (int j = 0; j < BQ; ++j) if (lab[j] == ml) { s += sn[j]; cnt++; }
    float cwm = (s / (float)cnt) * TALPHA + (1.0f - TALPHA) * 20.0f;
    float inv = 1.0f / (batch_std + EPSF);
    float ms = fminf(fmaxf((x - batch_mean) * inv * HF, -1.0f), 1.0f);
    d_gang[t] = -MMARG * ms;
    d_gadd[t] =  MMARG + MMARG * ms;
    out[(size_t)2 * BQ * CDIM + t] = fminf(fmaxf((x - cwm) * inv, -1.0f), 1.0f) * HF;
}

// ---------------------------------------------------------------------------
// K4: mma.sync bf16-split GEMM, 512 threads, double-buffered + reg prefetch.
// 16 warps (4m x 4n), warp tile 32x32.
// ---------------------------------------------------------------------------
__global__ void __launch_bounds__(512, 1)
gemm_kernel(const float* __restrict__ A,       // emb [512,512]
            const float* __restrict__ Kn,      // kernel t=0 plane (stride TWC)
            float* __restrict__ out) {
    extern __shared__ char smem[];
    const uint32_t sb = smem_u32(smem);
    float* ssqp = (float*)(smem + SSQP_OFF);
    float* sinv = (float*)(smem + SINV_OFF);

    const int t = threadIdx.x;
    const int lane = t & 31;
    const int wid = t >> 5;
    const int mbase = blockIdx.x * BM;
    const int cbase = blockIdx.y * BN;
    const int wm = (wid >> 2) * 32;
    const int wn = (wid & 3) * 32;

    float acc[2][4][4];
    #pragma unroll
    for (int i = 0; i < 2; ++i)
        #pragma unroll
        for (int j = 0; j < 4; ++j)
            #pragma unroll
            for (int r = 0; r < 4; ++r) acc[i][j][r] = 0.f;

    // B-load mapping: 4 threads per column, 8 k's each
    const int bn  = t & 127;
    const int bkh = (t >> 7) * 8;
    const int bc  = cbase + bn;
    const bool bvalid = bc < CDIM;
    float ssq = 0.f;

    // A-load mapping: 2 float4 per thread
    const int am0 = t >> 2,            aq0 = (t & 3) * 2;        // u = t*? no:
    // u0 = t      -> m = t>>3,       q = t&7
    // u1 = t+512  -> m = (t+512)>>3, q = t&7
    const int a_m0 = t >> 3, a_q = t & 7;
    const int a_m1 = a_m0 + 64;
    (void)am0; (void)aq0;

    // ldmatrix lane addressing
    const int a_row  = wm + (lane & 15);
    const int a_coff = (lane >> 4) * 8;
    const int b_n    = wn + ((lane >> 4) << 3) + (lane & 7);
    const int b_koff = ((lane >> 3) & 1) * 8;

    // prefetch registers
    float4 apre0, apre1;
    float  bpre[8];

    // ---- prologue: load chunk 0 ----
    {
        apre0 = *(const float4*)&A[(size_t)(mbase + a_m0) * EDIM + a_q * 4];
        apre1 = *(const float4*)&A[(size_t)(mbase + a_m1) * EDIM + a_q * 4];
        #pragma unroll
        for (int j = 0; j < 8; ++j)
            bpre[j] = bvalid ? Kn[(size_t)(bkh + j) * TWC + bc] : 0.f;
    }

    for (int ch = 0; ch < EDIM / BK; ++ch) {
        const int cur = ch & 1;
        const uint32_t cb = sb + cur * BUF_B;

        // ---- convert + store prefetched chunk into current buffer ----
        {
            uint16_t* Ah = (uint16_t*)(smem + cur * BUF_B);
            uint16_t* Al = (uint16_t*)(smem + cur * BUF_B + TILE_B);
            uint16_t* Bh = (uint16_t*)(smem + cur * BUF_B + 2 * TILE_B);
            uint16_t* Bl = (uint16_t*)(smem + cur * BUF_B + 3 * TILE_B);
            uint32_t h01, l01, h23, l23;
            split2(apre0.x, apre0.y, h01, l01);
            split2(apre0.z, apre0.w, h23, l23);
            *(uint2*)&Ah[a_m0 * RS + a_q * 4] = make_uint2(h01, h23);
            *(uint2*)&Al[a_m0 * RS + a_q * 4] = make_uint2(l01, l23);
            split2(apre1.x, apre1.y, h01, l01);
            split2(apre1.z, apre1.w, h23, l23);
            *(uint2*)&Ah[a_m1 * RS + a_q * 4] = make_uint2(h01, h23);
            *(uint2*)&Al[a_m1 * RS + a_q * 4] = make_uint2(l01, l23);
            #pragma unroll
            for (int j = 0; j < 8; j += 2) {
                ssq += bpre[j] * bpre[j] + bpre[j+1] * bpre[j+1];
                uint32_t hp, lp;
                split2(bpre[j], bpre[j+1], hp, lp);
                *(uint32_t*)&Bh[bn * RS + bkh + j] = hp;
                *(uint32_t*)&Bl[bn * RS + bkh + j] = lp;
            }
        }
        __syncthreads();

        // ---- issue global loads for next chunk (latency hidden by math) ----
        if (ch + 1 < EDIM / BK) {
            const int kb = (ch + 1) * BK;
            apre0 = *(const float4*)&A[(size_t)(mbase + a_m0) * EDIM + kb + a_q * 4];
            apre1 = *(const float4*)&A[(size_t)(mbase + a_m1) * EDIM + kb + a_q * 4];
            #pragma unroll
            for (int j = 0; j < 8; ++j)
                bpre[j] = bvalid ? Kn[(size_t)(kb + bkh + j) * TWC + bc] : 0.f;
        }

        // ---- math on current buffer ----
        const uint32_t aH = cb, aL = cb + TILE_B;
        const uint32_t bH = cb + 2 * TILE_B, bL = cb + 3 * TILE_B;
        #pragma unroll
        for (int kf = 0; kf < 2; ++kf) {
            const int kc = kf * 16;
            uint32_t ah[2][4], al[2][4], bhf[4][2], blf[4][2];
            #pragma unroll
            for (int mf = 0; mf < 2; ++mf) {
                uint32_t ad = ((uint32_t)((a_row + mf * 16) * RS + kc + a_coff)) * 2;
                ldsm4(ah[mf], aH + ad);
                ldsm4(al[mf], aL + ad);
            }
            {
                uint32_t bd0 = ((uint32_t)(b_n * RS + kc + b_koff)) * 2;
                uint32_t bd1 = ((uint32_t)((b_n + 16) * RS + kc + b_koff)) * 2;
                uint32_t r[4];
                ldsm4(r, bH + bd0);
                bhf[0][0]=r[0]; bhf[0][1]=r[1]; bhf[1][0]=r[2]; bhf[1][1]=r[3];
                ldsm4(r, bH + bd1);
                bhf[2][0]=r[0]; bhf[2][1]=r[1]; bhf[3][0]=r[2]; bhf[3][1]=r[3];
                ldsm4(r, bL + bd0);
                blf[0][0]=r[0]; blf[0][1]=r[1]; blf[1][0]=r[2]; blf[1][1]=r[3];
                ldsm4(r, bL + bd1);
                blf[2][0]=r[0]; blf[2][1]=r[1]; blf[3][0]=r[2]; blf[3][1]=r[3];
            }
            #pragma unroll
            for (int mf = 0; mf < 2; ++mf)
                #pragma unroll
                for (int nf = 0; nf < 4; ++nf)
                    mma_bf16(acc[mf][nf], ah[mf], bhf[nf]);
            #pragma unroll
            for (int mf = 0; mf < 2; ++mf)
                #pragma unroll
                for (int nf = 0; nf < 4; ++nf)
                    mma_bf16(acc[mf][nf], ah[mf], blf[nf]);
            #pragma unroll
            for (int mf = 0; mf < 2; ++mf)
                #pragma unroll
                for (int nf = 0; nf < 4; ++nf)
                    mma_bf16(acc[mf][nf], al[mf], bhf[nf]);
        }
        __syncthreads();
    }

    // ---- column inverse norms ----
    ssqp[t] = ssq;
    __syncthreads();
    if (t < 128)
        sinv[t] = rsqrtf(ssqp[t] + ssqp[t + 128] + ssqp[t + 256] + ssqp[t + 384]);
    __syncthreads();

    // ---- epilogue ----
    const float lo = -1.0f + EPSF, hi = 1.0f - EPSF;
    float inv[4][2];
    #pragma unroll
    for (int nf = 0; nf < 4; ++nf) {
        int c0 = wn + nf * 8 + (lane & 3) * 2;
        inv[nf][0] = sinv[c0];
        inv[nf][1] = sinv[c0 + 1];
    }
    #pragma unroll
    for (int mf = 0; mf < 2; ++mf) {
        int row0 = mbase + wm + mf * 16 + (lane >> 2);
        #pragma unroll
        for (int nf = 0; nf < 4; ++nf) {
            int col = cbase + wn + nf * 8 + (lane & 3) * 2;
            if (col < CDIM) {
                float v0 = fminf(fmaxf(acc[mf][nf][0] * inv[nf][0], lo), hi) * SF;
                float v1 = fminf(fmaxf(acc[mf][nf][1] * inv[nf][1], lo), hi) * SF;
                float v2 = fminf(fmaxf(acc[mf][nf][2] * inv[nf][0], lo), hi) * SF;
                float v3 = fminf(fmaxf(acc[mf][nf][3] * inv[nf][1], lo), hi) * SF;
                size_t o0 = (size_t)row0 * CDIM + col;
                size_t o1 = (size_t)(row0 + 8) * CDIM + col;
                *(float2*)(out + o0) = make_float2(v0, v1);
                *(float2*)(out + o1) = make_float2(v2, v3);
                *(float2*)(out + (size_t)BQ * CDIM + o0) = make_float2(v0, v1);
                *(float2*)(out + (size_t)BQ * CDIM + o1) = make_float2(v2, v3);
            }
        }
    }
}

// ---------------------------------------------------------------------------
// K5: label-column fixup
// ---------------------------------------------------------------------------
__global__ void fixup_kernel(const float* __restrict__ kern,
                             const float* __restrict__ emb,
                             const int*   __restrict__ label,
                             float* __restrict__ out) {
    int b = blockIdx.x, t = threadIdx.x;
    int lab = label[b];
    const float* col = kern + lab;
    float dt = 0.f, ss = 0.f;
    for (int e = t; e < EDIM; e += 128) {
        float v = col[(size_t)e * TWC];
        dt += emb[b * EDIM + e] * v;
        ss += v * v;
    }
    __shared__ float sdt[128], sss[128];
    sdt[t] = dt; sss[t] = ss;
    __syncthreads();
    for (int o = 64; o > 0; o >>= 1) {
        if (t < o) { sdt[t] += sdt[t+o]; sss[t] += sss[t+o]; }
        __syncthreads();
    }
    if (t == 0) {
        const float lo = -1.0f + EPSF, hi = 1.0f - EPSF;
        const float thlo = EPSF, thhi = (float)M_PI - EPSF;
        float gang = d_gang[b], gadd = d_gadd[b];
        float w1 = sdt[0] * rsqrtf(sss[0]);
        w1 = fminf(fmaxf(w1, lo), hi);
        float th1 = fminf(fmaxf(acosf(w1) + gang, thlo), thhi);
        out[(size_t)b * CDIM + lab] = (cosf(th1) - gadd) * SF;
        float w2 = d_cos2t[b];
        float th2 = fminf(fmaxf(acosf(w2) + gang, thlo), thhi);
        out[(size_t)BQ * CDIM + (size_t)b * CDIM + lab] = (cosf(th2) - gadd) * SF;
    }
}

// ---------------------------------------------------------------------------
extern "C" void kernel_launch(void* const* d_in, const int* in_sizes, int n_in,
                              void* d_out, int out_size) {
    const float* emb   = (const float*)d_in[0];  // [512, 512]
    const float* norms = (const float*)d_in[1];  // [512, 1]
    const int*   label = (const int*)  d_in[2];  // [512]
    const float* kern  = (const float*)d_in[3];  // [512, 2, 70722]
    float* out = (float*)d_out;

    cudaFuncSetAttribute(gemm_kernel,
                         cudaFuncAttributeMaxDynamicSharedMemorySize, SMEM_SZ);

    cos2_kernel<<<BQ, 128>>>(kern, emb, label);
    stats_kernel<<<1, BQ>>>(norms, label, out);
    gemm_kernel<<<dim3(4, (CDIM + BN - 1) / BN), 512, SMEM_SZ>>>(emb, kern, out);
    fixup_kernel<<<BQ, 128>>>(kern, emb, label, out);
}

// round 8
// speedup vs baseline: 3.0897x; 1.2967x over previous
#include <cuda_runtime.h>
#include <math.h>
#include <stdint.h>

// Problem constants
#define BQ    512
#define EDIM  512
#define CDIM  70722
#define TWC   (2*CDIM)
#define EPSF  0.001f
#define HF    0.333f
#define SF    64.0f
#define MMARG 0.4f
#define TALPHA 1.0f

// GEMM tile config
#define BM 128
#define BN 128
#define BK 32
#define RS 40                       // smem row stride in halves (80B)
#define TILE_H   (BM*RS)
#define TILE_B   (TILE_H*2)         // 10240 bytes per tile
#define BUF_B    (2*TILE_B)         // Ah,Bh = 20480 bytes per stage
#define SSQP_OFF (2*BUF_B)          // 40960
#define SINV_OFF (SSQP_OFF + 512*4) // 43008
#define SMEM_SZ  (SINV_OFF + BN*4)  // 43520

// Scratch
__device__ float d_cos2t[BQ];
__device__ float d_gang[BQ];
__device__ float d_gadd[BQ];

// ============================ helpers ======================================
__device__ __forceinline__ uint32_t smem_u32(const void* p) {
    uint32_t a;
    asm("{ .reg .u64 t; cvta.to.shared.u64 t, %1; cvt.u32.u64 %0, t; }" : "=r"(a) : "l"(p));
    return a;
}
__device__ __forceinline__ void ldsm4(uint32_t* r, uint32_t addr) {
    asm volatile("ldmatrix.sync.aligned.m8n8.x4.shared.b16 {%0,%1,%2,%3}, [%4];"
        : "=r"(r[0]), "=r"(r[1]), "=r"(r[2]), "=r"(r[3]) : "r"(addr));
}
__device__ __forceinline__ void mma_f16(float* c, const uint32_t* a, const uint32_t* b) {
    asm volatile(
        "mma.sync.aligned.m16n8k16.row.col.f32.f16.f16.f32 "
        "{%0,%1,%2,%3}, {%4,%5,%6,%7}, {%8,%9}, {%0,%1,%2,%3};"
        : "+f"(c[0]), "+f"(c[1]), "+f"(c[2]), "+f"(c[3])
        : "r"(a[0]), "r"(a[1]), "r"(a[2]), "r"(a[3]), "r"(b[0]), "r"(b[1]));
}
// pack (x0,x1) -> f16x2 (x0 in low half)
__device__ __forceinline__ uint32_t pack_f16(float x0, float x1) {
    uint32_t p;
    asm("cvt.rn.f16x2.f32 %0, %1, %2;" : "=r"(p) : "f"(x1), "f"(x0));
    return p;
}

// ---------------------------------------------------------------------------
// K2: cos2_tgt[b]
// ---------------------------------------------------------------------------
__global__ void cos2_kernel(const float* __restrict__ kern,
                            const float* __restrict__ emb,
                            const int*   __restrict__ label) {
    int b = blockIdx.x, t = threadIdx.x;
    int lab = label[b];
    const float* col = kern + (size_t)CDIM + lab;
    float ss = 0.f, dt = 0.f;
    for (int e = t; e < EDIM; e += 128) {
        float v = col[(size_t)e * TWC];
        ss += v * v;
        dt += emb[b * EDIM + e] * v;
    }
    __shared__ float sss[128], sdt[128];
    sss[t] = ss; sdt[t] = dt;
    __syncthreads();
    for (int o = 64; o > 0; o >>= 1) {
        if (t < o) { sss[t] += sss[t+o]; sdt[t] += sdt[t+o]; }
        __syncthreads();
    }
    if (t == 0) {
        float cz = sdt[0] * rsqrtf(sss[0]);
        d_cos2t[b] = fminf(fmaxf(cz, -1.0f + EPSF), 1.0f - EPSF);
    }
}

// ---------------------------------------------------------------------------
// K3: batch statistics + cw_margin output
// ---------------------------------------------------------------------------
__global__ void stats_kernel(const float* __restrict__ norms,
                             const int*   __restrict__ label,
                             float* __restrict__ out) {
    __shared__ float sn[BQ];
    __shared__ int   lab[BQ];
    __shared__ float red[BQ];
    int t = threadIdx.x;
    float x = fminf(fmaxf(norms[t], 0.001f), 100.0f);
    sn[t] = x; lab[t] = label[t]; red[t] = x;
    __syncthreads();
    for (int o = 256; o > 0; o >>= 1) { if (t < o) red[t] += red[t+o]; __syncthreads(); }
    float mean = red[0] * (1.0f / BQ);
    __syncthreads();
    float d = x - mean;
    red[t] = d * d;
    __syncthreads();
    for (int o = 256; o > 0; o >>= 1) { if (t < o) red[t] += red[t+o]; __syncthreads(); }
    float stdv = sqrtf(red[0] / (float)(BQ - 1));
    float batch_mean = mean * TALPHA + (1.0f - TALPHA) * 20.0f;
    float batch_std  = stdv * TALPHA + (1.0f - TALPHA) * 10.0f;
    int ml = lab[t];
    float s = 0.f; int cnt = 0;
    for (int j = 0; j < BQ; ++j) if (lab[j] == ml) { s += sn[j]; cnt++; }
    float cwm = (s / (float)cnt) * TALPHA + (1.0f - TALPHA) * 20.0f;
    float inv = 1.0f / (batch_std + EPSF);
    float ms = fminf(fmaxf((x - batch_mean) * inv * HF, -1.0f), 1.0f);
    d_gang[t] = -MMARG * ms;
    d_gadd[t] =  MMARG + MMARG * ms;
    out[(size_t)2 * BQ * CDIM + t] = fminf(fmaxf((x - cwm) * inv, -1.0f), 1.0f) * HF;
}

// ---------------------------------------------------------------------------
// K4: single-pass fp16 mma.sync GEMM, 512 threads, double-buffered.
// 16 warps (4m x 4n), warp tile 32x32.
// ---------------------------------------------------------------------------
__global__ void __launch_bounds__(512, 1)
gemm_kernel(const float* __restrict__ A,       // emb [512,512]
            const float* __restrict__ Kn,      // kernel t=0 plane (stride TWC)
            float* __restrict__ out) {
    extern __shared__ char smem[];
    const uint32_t sb = smem_u32(smem);
    float* ssqp = (float*)(smem + SSQP_OFF);
    float* sinv = (float*)(smem + SINV_OFF);

    const int t = threadIdx.x;
    const int lane = t & 31;
    const int wid = t >> 5;
    const int mbase = blockIdx.x * BM;
    const int cbase = blockIdx.y * BN;
    const int wm = (wid >> 2) * 32;
    const int wn = (wid & 3) * 32;

    float acc[2][4][4];
    #pragma unroll
    for (int i = 0; i < 2; ++i)
        #pragma unroll
        for (int j = 0; j < 4; ++j)
            #pragma unroll
            for (int r = 0; r < 4; ++r) acc[i][j][r] = 0.f;

    // B-load mapping: 4 threads per column, 8 k's each
    const int bn  = t & 127;
    const int bkh = (t >> 7) * 8;
    const int bc  = cbase + bn;
    const bool bvalid = bc < CDIM;
    float ssq = 0.f;

    // A-load mapping: 2 float4 per thread
    const int a_m0 = t >> 3, a_q = t & 7;
    const int a_m1 = a_m0 + 64;

    // ldmatrix lane addressing
    const int a_row  = wm + (lane & 15);
    const int a_coff = (lane >> 4) * 8;
    const int b_n    = wn + ((lane >> 4) << 3) + (lane & 7);
    const int b_koff = ((lane >> 3) & 1) * 8;

    // prefetch registers
    float4 apre0, apre1;
    float  bpre[8];

    // ---- prologue: load chunk 0 ----
    {
        apre0 = *(const float4*)&A[(size_t)(mbase + a_m0) * EDIM + a_q * 4];
        apre1 = *(const float4*)&A[(size_t)(mbase + a_m1) * EDIM + a_q * 4];
        #pragma unroll
        for (int j = 0; j < 8; ++j)
            bpre[j] = bvalid ? Kn[(size_t)(bkh + j) * TWC + bc] : 0.f;
    }

    for (int ch = 0; ch < EDIM / BK; ++ch) {
        const int cur = ch & 1;
        const uint32_t cb = sb + cur * BUF_B;

        // ---- convert + store prefetched chunk into current buffer ----
        {
            uint16_t* Ah = (uint16_t*)(smem + cur * BUF_B);
            uint16_t* Bh = (uint16_t*)(smem + cur * BUF_B + TILE_B);
            *(uint2*)&Ah[a_m0 * RS + a_q * 4] =
                make_uint2(pack_f16(apre0.x, apre0.y), pack_f16(apre0.z, apre0.w));
            *(uint2*)&Ah[a_m1 * RS + a_q * 4] =
                make_uint2(pack_f16(apre1.x, apre1.y), pack_f16(apre1.z, apre1.w));
            #pragma unroll
            for (int j = 0; j < 8; j += 2) {
                ssq += bpre[j] * bpre[j] + bpre[j+1] * bpre[j+1];
                *(uint32_t*)&Bh[bn * RS + bkh + j] = pack_f16(bpre[j], bpre[j+1]);
            }
        }
        __syncthreads();

        // ---- issue global loads for next chunk (latency hidden by math) ----
        if (ch + 1 < EDIM / BK) {
            const int kb = (ch + 1) * BK;
            apre0 = *(const float4*)&A[(size_t)(mbase + a_m0) * EDIM + kb + a_q * 4];
            apre1 = *(const float4*)&A[(size_t)(mbase + a_m1) * EDIM + kb + a_q * 4];
            #pragma unroll
            for (int j = 0; j < 8; ++j)
                bpre[j] = bvalid ? Kn[(size_t)(kb + bkh + j) * TWC + bc] : 0.f;
        }

        // ---- math on current buffer ----
        const uint32_t aH = cb;
        const uint32_t bH = cb + TILE_B;
        #pragma unroll
        for (int kf = 0; kf < 2; ++kf) {
            const int kc = kf * 16;
            uint32_t ah[2][4], bhf[4][2];
            #pragma unroll
            for (int mf = 0; mf < 2; ++mf) {
                uint32_t ad = ((uint32_t)((a_row + mf * 16) * RS + kc + a_coff)) * 2;
                ldsm4(ah[mf], aH + ad);
            }
            {
                uint32_t bd0 = ((uint32_t)(b_n * RS + kc + b_koff)) * 2;
                uint32_t bd1 = ((uint32_t)((b_n + 16) * RS + kc + b_koff)) * 2;
                uint32_t r[4];
                ldsm4(r, bH + bd0);
                bhf[0][0]=r[0]; bhf[0][1]=r[1]; bhf[1][0]=r[2]; bhf[1][1]=r[3];
                ldsm4(r, bH + bd1);
                bhf[2][0]=r[0]; bhf[2][1]=r[1]; bhf[3][0]=r[2]; bhf[3][1]=r[3];
            }
            #pragma unroll
            for (int mf = 0; mf < 2; ++mf)
                #pragma unroll
                for (int nf = 0; nf < 4; ++nf)
                    mma_f16(acc[mf][nf], ah[mf], bhf[nf]);
        }
        __syncthreads();
    }

    // ---- column inverse norms (fp32-exact) ----
    ssqp[t] = ssq;
    __syncthreads();
    if (t < 128)
        sinv[t] = rsqrtf(ssqp[t] + ssqp[t + 128] + ssqp[t + 256] + ssqp[t + 384]);
    __syncthreads();

    // ---- epilogue: clip*scale, dual-plane float2 stores ----
    const float lo = -1.0f + EPSF, hi = 1.0f - EPSF;
    float inv[4][2];
    #pragma unroll
    for (int nf = 0; nf < 4; ++nf) {
        int c0 = wn + nf * 8 + (lane & 3) * 2;
        inv[nf][0] = sinv[c0];
        inv[nf][1] = sinv[c0 + 1];
    }
    #pragma unroll
    for (int mf = 0; mf < 2; ++mf) {
        int row0 = mbase + wm + mf * 16 + (lane >> 2);
        #pragma unroll
        for (int nf = 0; nf < 4; ++nf) {
            int col = cbase + wn + nf * 8 + (lane & 3) * 2;
            if (col < CDIM) {
                float v0 = fminf(fmaxf(acc[mf][nf][0] * inv[nf][0], lo), hi) * SF;
                float v1 = fminf(fmaxf(acc[mf][nf][1] * inv[nf][1], lo), hi) * SF;
                float v2 = fminf(fmaxf(acc[mf][nf][2] * inv[nf][0], lo), hi) * SF;
                float v3 = fminf(fmaxf(acc[mf][nf][3] * inv[nf][1], lo), hi) * SF;
                size_t o0 = (size_t)row0 * CDIM + col;
                size_t o1 = (size_t)(row0 + 8) * CDIM + col;
                *(float2*)(out + o0) = make_float2(v0, v1);
                *(float2*)(out + o1) = make_float2(v2, v3);
                *(float2*)(out + (size_t)BQ * CDIM + o0) = make_float2(v0, v1);
                *(float2*)(out + (size_t)BQ * CDIM + o1) = make_float2(v2, v3);
            }
        }
    }
}

// ---------------------------------------------------------------------------
// K5: label-column fixup (fp32-exact)
// ---------------------------------------------------------------------------
__global__ void fixup_kernel(const float* __restrict__ kern,
                             const float* __restrict__ emb,
                             const int*   __restrict__ label,
                             float* __restrict__ out) {
    int b = blockIdx.x, t = threadIdx.x;
    int lab = label[b];
    const float* col = kern + lab;
    float dt = 0.f, ss = 0.f;
    for (int e = t; e < EDIM; e += 128) {
        float v = col[(size_t)e * TWC];
        dt += emb[b * EDIM + e] * v;
        ss += v * v;
    }
    __shared__ float sdt[128], sss[128];
    sdt[t] = dt; sss[t] = ss;
    __syncthreads();
    for (int o = 64; o > 0; o >>= 1) {
        if (t < o) { sdt[t] += sdt[t+o]; sss[t] += sss[t+o]; }
        __syncthreads();
    }
    if (t == 0) {
        const float lo = -1.0f + EPSF, hi = 1.0f - EPSF;
        const float thlo = EPSF, thhi = (float)M_PI - EPSF;
        float gang = d_gang[b], gadd = d_gadd[b];
        float w1 = sdt[0] * rsqrtf(sss[0]);
        w1 = fminf(fmaxf(w1, lo), hi);
        float th1 = fminf(fmaxf(acosf(w1) + gang, thlo), thhi);
        out[(size_t)b * CDIM + lab] = (cosf(th1) - gadd) * SF;
        float w2 = d_cos2t[b];
        float th2 = fminf(fmaxf(acosf(w2) + gang, thlo), thhi);
        out[(size_t)BQ * CDIM + (size_t)b * CDIM + lab] = (cosf(th2) - gadd) * SF;
    }
}

// ---------------------------------------------------------------------------
extern "C" void kernel_launch(void* const* d_in, const int* in_sizes, int n_in,
                              void* d_out, int out_size) {
    const float* emb   = (const float*)d_in[0];  // [512, 512]
    const float* norms = (const float*)d_in[1];  // [512, 1]
    const int*   label = (const int*)  d_in[2];  // [512]
    const float* kern  = (const float*)d_in[3];  // [512, 2, 70722]
    float* out = (float*)d_out;

    cudaFuncSetAttribute(gemm_kernel,
                         cudaFuncAttributeMaxDynamicSharedMemorySize, SMEM_SZ);

    cos2_kernel<<<BQ, 128>>>(kern, emb, label);
    stats_kernel<<<1, BQ>>>(norms, label, out);
    gemm_kernel<<<dim3(4, (CDIM + BN - 1) / BN), 512, SMEM_SZ>>>(emb, kern, out);
    fixup_kernel<<<BQ, 128>>>(kern, emb, label, out);
}